// round 1
// baseline (speedup 1.0000x reference)
#include <cuda_runtime.h>

#define BATCH 8
#define HH 2048
#define WW 2048
#define PATCH 16
#define DD 16
#define PH 128
#define PWp 128
#define FEAT 256
#define NPIX (PH * PWp)

// ---------------- device scratch (no allocations allowed) ----------------
__device__ float g_tc[256];                    // cos(2*pi*t/256)
__device__ float g_ts[256];                    // sin(2*pi*t/256)
__device__ float g_R[DD][FEAT];
__device__ float g_I[DD][FEAT];
__device__ float2 g_M[FEAT][DD / 2];           // M[f][k] as float2 pairs (16B-friendly)
__device__ float g_c[DD];
__device__ float g_img[BATCH * DD * NPIX];     // 8 MB intermediate image [b][d][i][j]
__device__ float g_ps[BATCH * DD * PH];        // per-row conv partial sums
__device__ float g_pq[BATCH * DD * PH];        // per-row conv partial sumsq
__device__ float g_mean[DD];
__device__ float g_rstd[DD];

// ---------------- packed f32x2 helpers (Blackwell) ----------------
__device__ __forceinline__ unsigned long long packf2(float lo, float hi) {
    unsigned long long r;
    asm("mov.b64 %0, {%1, %2};" : "=l"(r) : "f"(lo), "f"(hi));
    return r;
}
__device__ __forceinline__ void fmaf2(unsigned long long& d, unsigned long long a,
                                      unsigned long long b) {
    asm("fma.rn.f32x2 %0, %1, %2, %0;" : "+l"(d) : "l"(a), "l"(b));
}
__device__ __forceinline__ void unpackf2(unsigned long long v, float& lo, float& hi) {
    asm("mov.b64 {%0, %1}, %2;" : "=f"(lo), "=f"(hi) : "l"(v));
}

// ---------------- K0: sincos table ----------------
__global__ void k_table() {
    int t = threadIdx.x;
    float s, c;
    sincospif((float)t * (1.0f / 128.0f), &s, &c);  // 2*pi*t/256 = pi*t/128
    g_tc[t] = c;
    g_ts[t] = s;
}

// ---------------- K1: R[j,f], I[j,f] ----------------
__global__ void k_RI(const float* __restrict__ Wr, const float* __restrict__ Wi) {
    __shared__ float sc[256], ss[256], wr[256], wi[256];
    int f = threadIdx.x;
    int j = blockIdx.x;
    sc[f] = g_tc[f];
    ss[f] = g_ts[f];
    wr[f] = Wr[j * FEAT + f];
    wi[f] = Wi[j * FEAT + f];
    __syncthreads();
    float R = 0.f, I = 0.f;
    for (int d = 0; d < 256; ++d) {
        int t = (d * f) & 255;
        float cc = sc[t], s2 = ss[t];
        R += wr[d] * cc + wi[d] * s2;
        I += wi[d] * cc - wr[d] * s2;
    }
    g_R[j][f] = R;
    g_I[j][f] = I;
}

// ---------------- K2: M[f,k], c[k] ----------------
__global__ void k_M(const float* __restrict__ br, const float* __restrict__ bi) {
    int e = blockIdx.x * 256 + threadIdx.x;  // 4096 entries
    int f = e >> 4, k = e & 15;
    float m = 0.f;
    for (int j = 0; j < DD; ++j) {
        int t = (16 * j * k) & 255;
        m += g_R[j][f] * g_tc[t] - g_I[j][f] * g_ts[t];
    }
    ((float*)g_M)[f * DD + k] = m * (1.0f / 16.0f);
    if (e < DD) {
        float cc = 0.f;
        for (int j = 0; j < DD; ++j) {
            int t = (16 * j * e) & 255;
            cc += (br[j] - bi[j]) * g_tc[t] - (br[j] + bi[j]) * g_ts[t];
        }
        g_c[e] = cc * (1.0f / 16.0f);
    }
}

// ---------------- K3: main patch GEMM  y = p @ M + c ----------------
// grid = B*128 blocks (one per (b, patch-row)), 128 threads (one per patch col).
// Each thread reads its 16x16 patch directly (x is read exactly once overall)
// and accumulates 16 outputs in 8 packed f32x2 registers.
__global__ void __launch_bounds__(128) k_main(const float* __restrict__ x) {
    __shared__ unsigned long long sM[FEAT * 8];
    __shared__ float scc[DD];
    int tid = threadIdx.x;
    const unsigned long long* gm = (const unsigned long long*)g_M;
#pragma unroll
    for (int i = 0; i < 16; ++i) sM[tid + i * 128] = gm[tid + i * 128];
    if (tid < DD) scc[tid] = g_c[tid];
    __syncthreads();

    int blk = blockIdx.x;
    int b = blk >> 7, ph = blk & 127;
    const float* xb = x + (size_t)(b * HH + ph * PATCH) * WW + tid * PATCH;

    unsigned long long acc[8];
#pragma unroll
    for (int m = 0; m < 8; ++m) acc[m] = packf2(scc[2 * m], scc[2 * m + 1]);

#pragma unroll 1
    for (int s1 = 0; s1 < PATCH; ++s1) {
        const float4* row = (const float4*)(xb + (size_t)s1 * WW);
#pragma unroll
        for (int q = 0; q < 4; ++q) {
            float4 v = row[q];
            const unsigned long long* m0 = &sM[(s1 * 16 + q * 4) * 8];
            unsigned long long vp;
            vp = packf2(v.x, v.x);
#pragma unroll
            for (int m = 0; m < 8; ++m) fmaf2(acc[m], vp, m0[m]);
            vp = packf2(v.y, v.y);
#pragma unroll
            for (int m = 0; m < 8; ++m) fmaf2(acc[m], vp, m0[8 + m]);
            vp = packf2(v.z, v.z);
#pragma unroll
            for (int m = 0; m < 8; ++m) fmaf2(acc[m], vp, m0[16 + m]);
            vp = packf2(v.w, v.w);
#pragma unroll
            for (int m = 0; m < 8; ++m) fmaf2(acc[m], vp, m0[24 + m]);
        }
    }

    float* outp = g_img + (size_t)b * DD * NPIX + ph * PWp + tid;
#pragma unroll
    for (int m = 0; m < 8; ++m) {
        float lo, hi;
        unpackf2(acc[m], lo, hi);
        outp[(2 * m) * NPIX] = lo;
        outp[(2 * m + 1) * NPIX] = hi;
    }
}

// ---------------- depthwise 3x3 conv value (zero pad, no kernel flip) ----------------
__device__ __forceinline__ float conv_at(const float* __restrict__ base, int i, int j,
                                         const float* w, float bias) {
    float val = bias;
#pragma unroll
    for (int r = 0; r < 3; ++r) {
        int ii = i + r - 1;
        if ((unsigned)ii < 128u) {
            const float* rowp = base + ii * 128;
#pragma unroll
            for (int c = 0; c < 3; ++c) {
                int jj = j + c - 1;
                if ((unsigned)jj < 128u) val += rowp[jj] * w[r * 3 + c];
            }
        }
    }
    return val;
}

// ---------------- K4: conv + per-row partial stats (deterministic) ----------------
__global__ void __launch_bounds__(128) k_stats(const float* __restrict__ cw,
                                               const float* __restrict__ cb) {
    int blk = blockIdx.x;       // ((b*16 + d)*128 + i)
    int i = blk & 127;
    int bd = blk >> 7;
    int d = bd & 15;
    int j = threadIdx.x;
    float w[9];
#pragma unroll
    for (int t = 0; t < 9; ++t) w[t] = cw[d * 9 + t];
    const float* base = g_img + (size_t)bd * NPIX;
    float val = conv_at(base, i, j, w, cb[d]);
    float v2 = val * val;
#pragma unroll
    for (int off = 16; off; off >>= 1) {
        val += __shfl_down_sync(0xffffffffu, val, off);
        v2 += __shfl_down_sync(0xffffffffu, v2, off);
    }
    __shared__ float ss[4], sq[4];
    if ((j & 31) == 0) {
        ss[j >> 5] = val;
        sq[j >> 5] = v2;
    }
    __syncthreads();
    if (j == 0) {
        g_ps[blk] = ss[0] + ss[1] + ss[2] + ss[3];
        g_pq[blk] = sq[0] + sq[1] + sq[2] + sq[3];
    }
}

// ---------------- K5: finalize BN stats (deterministic tree reduce) ----------------
__global__ void k_finalize() {
    int d = blockIdx.x;
    int t = threadIdx.x;  // 256
    double s = 0.0, q = 0.0;
    for (int e = t; e < 1024; e += 256) {
        int b = e >> 7, i = e & 127;
        int idx = (b * DD + d) * PH + i;
        s += (double)g_ps[idx];
        q += (double)g_pq[idx];
    }
    __shared__ double sh_s[256], sh_q[256];
    sh_s[t] = s;
    sh_q[t] = q;
    __syncthreads();
    for (int off = 128; off; off >>= 1) {
        if (t < off) {
            sh_s[t] += sh_s[t + off];
            sh_q[t] += sh_q[t + off];
        }
        __syncthreads();
    }
    if (t == 0) {
        double n = 131072.0;
        double mu = sh_s[0] / n;
        double var = sh_q[0] / n - mu * mu;
        g_mean[d] = (float)mu;
        g_rstd[d] = rsqrtf((float)var + 1e-5f);
    }
}

// ---------------- K6: conv (recompute) + BN apply + identity interp + write out ----
__global__ void __launch_bounds__(128) k_out(const float* __restrict__ cw,
                                             const float* __restrict__ cb,
                                             const float* __restrict__ gamma,
                                             const float* __restrict__ beta,
                                             float* __restrict__ out) {
    int blk = blockIdx.x;
    int i = blk & 127;
    int bd = blk >> 7;
    int d = bd & 15;
    int j = threadIdx.x;
    float w[9];
#pragma unroll
    for (int t = 0; t < 9; ++t) w[t] = cw[d * 9 + t];
    const float* base = g_img + (size_t)bd * NPIX;
    float val = conv_at(base, i, j, w, cb[d]);
    float res = (val - g_mean[d]) * g_rstd[d] * gamma[d] + beta[d];
    // out layout [b][d][i][j]; interp is identity since h=w=OUT=128
    out[(size_t)blk * 128 + j] = res;
}

extern "C" void kernel_launch(void* const* d_in, const int* in_sizes, int n_in,
                              void* d_out, int out_size) {
    const float* x = (const float*)d_in[0];
    const float* Wr = (const float*)d_in[1];
    const float* br = (const float*)d_in[2];
    const float* Wi = (const float*)d_in[3];
    const float* bi = (const float*)d_in[4];
    const float* cw = (const float*)d_in[5];
    const float* cb = (const float*)d_in[6];
    const float* gamma = (const float*)d_in[7];
    const float* beta = (const float*)d_in[8];
    float* out = (float*)d_out;

    k_table<<<1, 256>>>();
    k_RI<<<16, 256>>>(Wr, Wi);
    k_M<<<16, 256>>>(br, bi);
    k_main<<<BATCH * PH, 128>>>(x);
    k_stats<<<BATCH * DD * PH, 128>>>(cw, cb);
    k_finalize<<<DD, 256>>>();
    k_out<<<BATCH * DD * PH, 128>>>(cw, cb, gamma, beta, out);
}

// round 2
// speedup vs baseline: 1.1286x; 1.1286x over previous
#include <cuda_runtime.h>

#define BATCH 8
#define HH 2048
#define WW 2048
#define PATCH 16
#define DD 16
#define PH 128
#define PWp 128
#define FEAT 256
#define NPIX (PH * PWp)

typedef unsigned long long ull;
typedef unsigned int uint;

// ---------------- device scratch ----------------
__device__ float g_tc[256];
__device__ float g_ts[256];
__device__ float g_R[DD][FEAT];
__device__ float g_I[DD][FEAT];
__device__ __align__(16) float2 g_M[FEAT][DD / 2];   // M[f][k] pairs along k
__device__ float g_c[DD];
__device__ float g_img[BATCH * DD * NPIX];           // 8 MB [b][d][i][j]
__device__ float g_ps[1024];                          // conv partial sums (512 used)
__device__ float g_pq[1024];
__device__ float g_mean[DD];
__device__ float g_rstd[DD];

// ---------------- packed f32x2 helpers ----------------
__device__ __forceinline__ ull packf2(float lo, float hi) {
    ull r; asm("mov.b64 %0, {%1, %2};" : "=l"(r) : "f"(lo), "f"(hi)); return r;
}
__device__ __forceinline__ void fmaf2(ull& d, ull a, ull b) {
    asm("fma.rn.f32x2 %0, %1, %2, %0;" : "+l"(d) : "l"(a), "l"(b));
}
__device__ __forceinline__ ull addf2(ull a, ull b) {
    ull r; asm("add.rn.f32x2 %0, %1, %2;" : "=l"(r) : "l"(a), "l"(b)); return r;
}
__device__ __forceinline__ void unpackf2(ull v, float& lo, float& hi) {
    asm("mov.b64 {%0, %1}, %2;" : "=f"(lo), "=f"(hi) : "l"(v));
}
__device__ __forceinline__ void lds_v2u64(ull& a, ull& b, uint addr) {
    asm volatile("ld.shared.v2.u64 {%0, %1}, [%2];" : "=l"(a), "=l"(b) : "r"(addr));
}

// ---------------- K0: sincos table ----------------
__global__ void k_table() {
    int t = threadIdx.x;
    float s, c;
    sincospif((float)t * (1.0f / 128.0f), &s, &c);
    g_tc[t] = c; g_ts[t] = s;
}

// ---------------- K1: R[j,f], I[j,f] ----------------
__global__ void k_RI(const float* __restrict__ Wr, const float* __restrict__ Wi) {
    __shared__ float sc[256], ss[256], wr[256], wi[256];
    int f = threadIdx.x, j = blockIdx.x;
    sc[f] = g_tc[f]; ss[f] = g_ts[f];
    wr[f] = Wr[j * FEAT + f]; wi[f] = Wi[j * FEAT + f];
    __syncthreads();
    float R = 0.f, I = 0.f;
    for (int d = 0; d < 256; ++d) {
        int t = (d * f) & 255;
        float cc = sc[t], s2 = ss[t];
        R += wr[d] * cc + wi[d] * s2;
        I += wi[d] * cc - wr[d] * s2;
    }
    g_R[j][f] = R; g_I[j][f] = I;
}

// ---------------- K2: M[f,k], c[k] ----------------
__global__ void k_M(const float* __restrict__ br, const float* __restrict__ bi) {
    int e = blockIdx.x * 256 + threadIdx.x;
    int f = e >> 4, k = e & 15;
    float m = 0.f;
    for (int j = 0; j < DD; ++j) {
        int t = (16 * j * k) & 255;
        m += g_R[j][f] * g_tc[t] - g_I[j][f] * g_ts[t];
    }
    ((float*)g_M)[f * DD + k] = m * (1.0f / 16.0f);
    if (e < DD) {
        float cc = 0.f;
        for (int j = 0; j < DD; ++j) {
            int t = (16 * j * e) & 255;
            cc += (br[j] - bi[j]) * g_tc[t] - (br[j] + bi[j]) * g_ts[t];
        }
        g_c[e] = cc * (1.0f / 16.0f);
    }
}

// ---------------- K3: main patch GEMM, warp = 16 adjacent patches -------------
// lane l: a = l>>2 (patch pair a and 8+a within the 16-patch segment),
//         q = l&3 (s2 quad). Per s1: 2 coalesced LDG.128 cover 1024B.
// M rows read as LDS.128 (v2.u64) from swizzled smem (conflict-free).
// 2-round shfl.xor reduce-scatter over the 4 quad-lanes.
__global__ void __launch_bounds__(256) k_main(const float* __restrict__ x) {
    __shared__ uint4 sM[FEAT * 4];   // row f: 4 x 16B units, unit m at col (m+(f>>2))&3
    __shared__ float scc[DD];
    int tid = threadIdx.x;
    {   // stage swizzled M
        const uint4* gm = (const uint4*)g_M;
        int f = tid;
#pragma unroll
        for (int m = 0; m < 4; ++m)
            sM[f * 4 + ((m + (f >> 2)) & 3)] = gm[f * 4 + m];
        if (tid < DD) scc[tid] = g_c[tid];
    }
    __syncthreads();

    uint sMaddr = (uint)__cvta_generic_to_shared(sM);

    int lane = tid & 31;
    int warp = tid >> 5;
    int u = blockIdx.x * 8 + warp;          // 8192 warp units
    int b = u >> 10;
    int r = u & 1023;
    int ph = r >> 3;                        // patch row
    int seg = r & 7;                        // 16-patch column segment
    int a = lane >> 2;
    int q = lane & 3;

    const float* base = x + (size_t)b * HH * WW + (size_t)(ph * PATCH) * WW + seg * 256;

    ull accA[8], accB[8];
    ull z = packf2(0.f, 0.f);
#pragma unroll
    for (int k2 = 0; k2 < 8; ++k2) { accA[k2] = z; accB[k2] = z; }

    const float4* rp = (const float4*)base;
    float4 curA = rp[lane];
    float4 curB = rp[32 + lane];

#pragma unroll 1
    for (int s1 = 0; s1 < PATCH; ++s1) {
        float4 nA, nB;
        if (s1 < 15) {
            const float4* rn = (const float4*)(base + (size_t)(s1 + 1) * WW);
            nA = rn[lane]; nB = rn[32 + lane];
        }
        uint rowbase = sMaddr + (uint)(s1 * 16 + q * 4) * 64;
#pragma unroll
        for (int e = 0; e < 4; ++e) {
            float xa = (e == 0) ? curA.x : (e == 1) ? curA.y : (e == 2) ? curA.z : curA.w;
            float xb = (e == 0) ? curB.x : (e == 1) ? curB.y : (e == 2) ? curB.z : curB.w;
            uint ra = rowbase + (uint)e * 64;
            ull mk[8];
#pragma unroll
            for (int m = 0; m < 4; ++m)
                lds_v2u64(mk[2 * m], mk[2 * m + 1], ra + (uint)(((m + q) & 3) << 4));
            ull vpa = packf2(xa, xa);
            ull vpb = packf2(xb, xb);
#pragma unroll
            for (int k2 = 0; k2 < 8; ++k2) {
                fmaf2(accA[k2], vpa, mk[k2]);
                fmaf2(accB[k2], vpb, mk[k2]);
            }
        }
        curA = nA; curB = nB;
    }

    // reduce-scatter over quad lanes: round1 xor1, round2 xor2
    ull tA[4], tB[4], fA[2], fB[2];
#pragma unroll
    for (int j = 0; j < 4; ++j) {
        ull sendA = (q & 1) ? accA[j] : accA[j + 4];
        ull keepA = (q & 1) ? accA[j + 4] : accA[j];
        ull sendB = (q & 1) ? accB[j] : accB[j + 4];
        ull keepB = (q & 1) ? accB[j + 4] : accB[j];
        tA[j] = addf2(keepA, __shfl_xor_sync(0xffffffffu, sendA, 1));
        tB[j] = addf2(keepB, __shfl_xor_sync(0xffffffffu, sendB, 1));
    }
#pragma unroll
    for (int j = 0; j < 2; ++j) {
        ull sendA = (q & 2) ? tA[j] : tA[j + 2];
        ull keepA = (q & 2) ? tA[j + 2] : tA[j];
        ull sendB = (q & 2) ? tB[j] : tB[j + 2];
        ull keepB = (q & 2) ? tB[j + 2] : tB[j];
        fA[j] = addf2(keepA, __shfl_xor_sync(0xffffffffu, sendA, 2));
        fB[j] = addf2(keepB, __shfl_xor_sync(0xffffffffu, sendB, 2));
    }
    // lane holds k2 = kb, kb+1 with kb = ((q&1)<<2) | (q&2)
    int kb = ((q & 1) << 2) | (q & 2);
    float* gp = g_img + (size_t)b * DD * NPIX + ph * PWp + seg * 16;
#pragma unroll
    for (int j = 0; j < 2; ++j) {
        int k2 = kb + j;
        int k0 = 2 * k2;
        ull cb = packf2(scc[k0], scc[k0 + 1]);
        ull va = addf2(fA[j], cb);
        ull vb = addf2(fB[j], cb);
        float a0, a1, b0, b1;
        unpackf2(va, a0, a1);
        unpackf2(vb, b0, b1);
        gp[(size_t)k0 * NPIX + a] = a0;
        gp[(size_t)(k0 + 1) * NPIX + a] = a1;
        gp[(size_t)k0 * NPIX + 8 + a] = b0;
        gp[(size_t)(k0 + 1) * NPIX + 8 + a] = b1;
    }
}

// ---------------- tiled depthwise conv helpers ----------------
#define TSTRIDE 136   // 128 data cols at offset 4, zero borders, 16B-aligned rows

__device__ __forceinline__ void load_tile(float* tile, const float* __restrict__ base,
                                          int r0, int tid) {
    for (int i = tid; i < 34 * TSTRIDE; i += 128) tile[i] = 0.f;
    __syncthreads();
    for (int idx = tid; idx < 34 * 32; idx += 128) {
        int rr = idx >> 5, c = idx & 31;
        int gi = r0 - 1 + rr;
        if (gi >= 0 && gi < 128)
            *(float4*)&tile[rr * TSTRIDE + 4 + 4 * c] =
                *(const float4*)&base[gi * 128 + 4 * c];
    }
    __syncthreads();
}

// ---------------- K4: conv + per-block partial stats ----------------
__global__ void __launch_bounds__(128) k_stats(const float* __restrict__ cw,
                                               const float* __restrict__ cb) {
    __shared__ float tile[34 * TSTRIDE];
    __shared__ float rs[4], rq[4];
    int blk = blockIdx.x;           // bd*4 + part
    int bd = blk >> 2;
    int d = bd & 15;
    int r0 = (blk & 3) * 32;
    int tid = threadIdx.x;
    float w[9];
#pragma unroll
    for (int t = 0; t < 9; ++t) w[t] = cw[d * 9 + t];
    float bias = cb[d];
    load_tile(tile, g_img + (size_t)bd * NPIX, r0, tid);

    const float* tb = tile + 4 + tid;
    float a0 = tb[-1], a1 = tb[0], a2 = tb[1];
    float b0 = tb[TSTRIDE - 1], b1 = tb[TSTRIDE], b2 = tb[TSTRIDE + 1];
    float s = 0.f, sq = 0.f;
#pragma unroll 4
    for (int oi = 0; oi < 32; ++oi) {
        const float* rw = tb + (oi + 2) * TSTRIDE;
        float c0 = rw[-1], c1 = rw[0], c2 = rw[1];
        float v = bias + a0 * w[0] + a1 * w[1] + a2 * w[2]
                       + b0 * w[3] + b1 * w[4] + b2 * w[5]
                       + c0 * w[6] + c1 * w[7] + c2 * w[8];
        s += v; sq += v * v;
        a0 = b0; a1 = b1; a2 = b2;
        b0 = c0; b1 = c1; b2 = c2;
    }
#pragma unroll
    for (int off = 16; off; off >>= 1) {
        s += __shfl_down_sync(0xffffffffu, s, off);
        sq += __shfl_down_sync(0xffffffffu, sq, off);
    }
    if ((tid & 31) == 0) { rs[tid >> 5] = s; rq[tid >> 5] = sq; }
    __syncthreads();
    if (tid == 0) {
        g_ps[blk] = rs[0] + rs[1] + rs[2] + rs[3];
        g_pq[blk] = rq[0] + rq[1] + rq[2] + rq[3];
    }
}

// ---------------- K5: finalize BN stats (one warp per d) ----------------
__global__ void k_finalize() {
    int d = threadIdx.x >> 5;
    int lane = threadIdx.x & 31;
    int b = lane >> 2, p = lane & 3;
    double s = (double)g_ps[(b * DD + d) * 4 + p];
    double q = (double)g_pq[(b * DD + d) * 4 + p];
#pragma unroll
    for (int off = 16; off; off >>= 1) {
        s += __shfl_down_sync(0xffffffffu, s, off);
        q += __shfl_down_sync(0xffffffffu, q, off);
    }
    if (lane == 0) {
        double n = 131072.0;
        double mu = s / n;
        double var = q / n - mu * mu;
        g_mean[d] = (float)mu;
        g_rstd[d] = rsqrtf((float)var + 1e-5f);
    }
}

// ---------------- K6: conv (recompute) + BN apply + write out ----------------
__global__ void __launch_bounds__(128) k_out(const float* __restrict__ cw,
                                             const float* __restrict__ cb,
                                             const float* __restrict__ gamma,
                                             const float* __restrict__ beta,
                                             float* __restrict__ out) {
    __shared__ float tile[34 * TSTRIDE];
    int blk = blockIdx.x;
    int bd = blk >> 2;
    int d = bd & 15;
    int r0 = (blk & 3) * 32;
    int tid = threadIdx.x;
    float w[9];
#pragma unroll
    for (int t = 0; t < 9; ++t) w[t] = cw[d * 9 + t];
    float bias = cb[d];
    float mu = g_mean[d];
    float sc = g_rstd[d] * gamma[d];
    float bt = beta[d];
    load_tile(tile, g_img + (size_t)bd * NPIX, r0, tid);

    const float* tb = tile + 4 + tid;
    float a0 = tb[-1], a1 = tb[0], a2 = tb[1];
    float b0 = tb[TSTRIDE - 1], b1 = tb[TSTRIDE], b2 = tb[TSTRIDE + 1];
    float* op = out + (size_t)bd * NPIX + (size_t)r0 * 128 + tid;
#pragma unroll 4
    for (int oi = 0; oi < 32; ++oi) {
        const float* rw = tb + (oi + 2) * TSTRIDE;
        float c0 = rw[-1], c1 = rw[0], c2 = rw[1];
        float v = bias + a0 * w[0] + a1 * w[1] + a2 * w[2]
                       + b0 * w[3] + b1 * w[4] + b2 * w[5]
                       + c0 * w[6] + c1 * w[7] + c2 * w[8];
        op[oi * 128] = (v - mu) * sc + bt;
        a0 = b0; a1 = b1; a2 = b2;
        b0 = c0; b1 = c1; b2 = c2;
    }
}

extern "C" void kernel_launch(void* const* d_in, const int* in_sizes, int n_in,
                              void* d_out, int out_size) {
    const float* x = (const float*)d_in[0];
    const float* Wr = (const float*)d_in[1];
    const float* br = (const float*)d_in[2];
    const float* Wi = (const float*)d_in[3];
    const float* bi = (const float*)d_in[4];
    const float* cw = (const float*)d_in[5];
    const float* cb = (const float*)d_in[6];
    const float* gamma = (const float*)d_in[7];
    const float* beta = (const float*)d_in[8];
    float* out = (float*)d_out;

    k_table<<<1, 256>>>();
    k_RI<<<16, 256>>>(Wr, Wi);
    k_M<<<16, 256>>>(br, bi);
    k_main<<<1024, 256>>>(x);
    k_stats<<<BATCH * DD * 4, 128>>>(cw, cb);
    k_finalize<<<1, 512>>>();
    k_out<<<BATCH * DD * 4, 128>>>(cw, cb, gamma, beta, out);
}

// round 3
// speedup vs baseline: 1.3502x; 1.1964x over previous
#include <cuda_runtime.h>

#define BATCH 8
#define HH 2048
#define WW 2048
#define PATCH 16
#define DD 16
#define PH 128
#define FEAT 256
#define NPIX (128 * 128)

typedef unsigned long long ull;
typedef unsigned int uint;

// ---------------- device scratch ----------------
__device__ float g_tc[256];
__device__ float g_ts[256];
__device__ float g_R[DD][FEAT];
__device__ float g_I[DD][FEAT];
__device__ __align__(16) float2 g_M[FEAT][DD / 2];   // M[f][k] pairs along k
__device__ float g_c[DD];
__device__ float g_img[BATCH * DD * NPIX];           // 8 MB [b][d][i][j]
__device__ float g_ps[256];                          // conv partial sums [bd*2+half]
__device__ float g_pq[256];

// ---------------- packed f32x2 helpers ----------------
__device__ __forceinline__ ull packf2(float lo, float hi) {
    ull r; asm("mov.b64 %0, {%1, %2};" : "=l"(r) : "f"(lo), "f"(hi)); return r;
}
__device__ __forceinline__ void fmaf2(ull& d, ull a, ull b) {
    asm("fma.rn.f32x2 %0, %1, %2, %0;" : "+l"(d) : "l"(a), "l"(b));
}
__device__ __forceinline__ ull addf2(ull a, ull b) {
    ull r; asm("add.rn.f32x2 %0, %1, %2;" : "=l"(r) : "l"(a), "l"(b)); return r;
}
__device__ __forceinline__ void unpackf2(ull v, float& lo, float& hi) {
    asm("mov.b64 {%0, %1}, %2;" : "=f"(lo), "=f"(hi) : "l"(v));
}
__device__ __forceinline__ void lds_v2u64(ull& a, ull& b, uint addr) {
    asm volatile("ld.shared.v2.u64 {%0, %1}, [%2];" : "=l"(a), "=l"(b) : "r"(addr));
}

// ---------------- K1: table + R[j,f], I[j,f] ----------------
__global__ void k_prep1(const float* __restrict__ Wr, const float* __restrict__ Wi) {
    __shared__ float sc[256], ss[256], wr[256], wi[256];
    int f = threadIdx.x, j = blockIdx.x;
    float s, c;
    sincospif((float)f * (1.0f / 128.0f), &s, &c);
    sc[f] = c; ss[f] = s;
    if (j == 0) { g_tc[f] = c; g_ts[f] = s; }
    wr[f] = Wr[j * FEAT + f]; wi[f] = Wi[j * FEAT + f];
    __syncthreads();
    float R = 0.f, I = 0.f;
    for (int d = 0; d < 256; ++d) {
        int t = (d * f) & 255;
        float cc = sc[t], s2 = ss[t];
        R += wr[d] * cc + wi[d] * s2;
        I += wi[d] * cc - wr[d] * s2;
    }
    g_R[j][f] = R; g_I[j][f] = I;
}

// ---------------- K2: M[f,k], c[k] ----------------
__global__ void k_prep2(const float* __restrict__ br, const float* __restrict__ bi) {
    int e = blockIdx.x * 256 + threadIdx.x;
    int f = e >> 4, k = e & 15;
    float m = 0.f;
    for (int j = 0; j < DD; ++j) {
        int t = (16 * j * k) & 255;
        m += g_R[j][f] * g_tc[t] - g_I[j][f] * g_ts[t];
    }
    ((float*)g_M)[f * DD + k] = m * (1.0f / 16.0f);
    if (e < DD) {
        float cc = 0.f;
        for (int j = 0; j < DD; ++j) {
            int t = (16 * j * e) & 255;
            cc += (br[j] - bi[j]) * g_tc[t] - (br[j] + bi[j]) * g_ts[t];
        }
        g_c[e] = cc * (1.0f / 16.0f);
    }
}

// ---------------- K3: main patch GEMM, warp = 32 adjacent patches -------------
// lane l: a = l>>2, q = l&3 (s2 quad). Streams t=0..3 cover patches t*8+a.
// Per s1: 4 coalesced LDG.128 (2KB contiguous per warp).
// M rows via swizzled LDS.128 (v2.u64); amortized over 4 streams.
__global__ void __launch_bounds__(128, 4) k_main(const float* __restrict__ x) {
    __shared__ uint4 sM[FEAT * 4];   // row f: unit m stored at col (m+(f>>2))&3
    __shared__ float scc[DD];
    int tid = threadIdx.x;
    {
        const uint4* gm = (const uint4*)g_M;
        for (int f = tid; f < 256; f += 128)
#pragma unroll
            for (int m = 0; m < 4; ++m)
                sM[f * 4 + ((m + (f >> 2)) & 3)] = gm[f * 4 + m];
        if (tid < DD) scc[tid] = g_c[tid];
    }
    __syncthreads();

    uint sMaddr = (uint)__cvta_generic_to_shared(sM);
    int lane = tid & 31;
    int warp = tid >> 5;
    int u = blockIdx.x * 4 + warp;          // 4096 warp units
    int b = u >> 9;
    int r = u & 511;
    int ph = r >> 2;                        // patch row
    int seg = r & 3;                        // 32-patch column segment
    int a = lane >> 2;
    int q = lane & 3;

    const float* base = x + (size_t)b * HH * WW + (size_t)(ph * PATCH) * WW + seg * 512;

    ull acc[4][8];
    ull z = packf2(0.f, 0.f);
#pragma unroll
    for (int t = 0; t < 4; ++t)
#pragma unroll
        for (int k2 = 0; k2 < 8; ++k2) acc[t][k2] = z;

    const float4* rp = (const float4*)base;
    float4 cur[4];
#pragma unroll
    for (int t = 0; t < 4; ++t) cur[t] = rp[t * 32 + lane];

#pragma unroll 1
    for (int s1 = 0; s1 < PATCH; ++s1) {
        float4 nxt[4];
        if (s1 < 15) {
            const float4* rn = (const float4*)(base + (size_t)(s1 + 1) * WW);
#pragma unroll
            for (int t = 0; t < 4; ++t) nxt[t] = rn[t * 32 + lane];
        }
        uint rowbase = sMaddr + (uint)(s1 * 16 + q * 4) * 64;
#pragma unroll
        for (int e = 0; e < 4; ++e) {
            uint ra = rowbase + (uint)e * 64;
            ull vp[4];
#pragma unroll
            for (int t = 0; t < 4; ++t) {
                float xv = (e == 0) ? cur[t].x : (e == 1) ? cur[t].y
                         : (e == 2) ? cur[t].z : cur[t].w;
                vp[t] = packf2(xv, xv);
            }
            // half A: k-pairs 0..3
            {
                ull mk[4];
                lds_v2u64(mk[0], mk[1], ra + (uint)(((0 + q) & 3) << 4));
                lds_v2u64(mk[2], mk[3], ra + (uint)(((1 + q) & 3) << 4));
#pragma unroll
                for (int t = 0; t < 4; ++t)
#pragma unroll
                    for (int k2 = 0; k2 < 4; ++k2) fmaf2(acc[t][k2], vp[t], mk[k2]);
            }
            // half B: k-pairs 4..7
            {
                ull mk[4];
                lds_v2u64(mk[0], mk[1], ra + (uint)(((2 + q) & 3) << 4));
                lds_v2u64(mk[2], mk[3], ra + (uint)(((3 + q) & 3) << 4));
#pragma unroll
                for (int t = 0; t < 4; ++t)
#pragma unroll
                    for (int k2 = 0; k2 < 4; ++k2) fmaf2(acc[t][k2 + 4], vp[t], mk[k2]);
            }
        }
        if (s1 < 15) {
#pragma unroll
            for (int t = 0; t < 4; ++t) cur[t] = nxt[t];
        }
    }

    // reduce-scatter over quad lanes: round1 xor1, round2 xor2
    int kb = ((q & 1) << 2) | (q & 2);
#pragma unroll
    for (int t = 0; t < 4; ++t) {
        ull tmp[4], fin[2];
#pragma unroll
        for (int j = 0; j < 4; ++j) {
            ull send = (q & 1) ? acc[t][j] : acc[t][j + 4];
            ull keep = (q & 1) ? acc[t][j + 4] : acc[t][j];
            tmp[j] = addf2(keep, __shfl_xor_sync(0xffffffffu, send, 1));
        }
#pragma unroll
        for (int j = 0; j < 2; ++j) {
            ull send = (q & 2) ? tmp[j] : tmp[j + 2];
            ull keep = (q & 2) ? tmp[j + 2] : tmp[j];
            fin[j] = addf2(keep, __shfl_xor_sync(0xffffffffu, send, 2));
        }
        int col = seg * 32 + t * 8 + a;
        float* gp = g_img + (size_t)b * DD * NPIX + ph * 128 + col;
#pragma unroll
        for (int j = 0; j < 2; ++j) {
            int k0 = 2 * (kb + j);
            ull va = addf2(fin[j], packf2(scc[k0], scc[k0 + 1]));
            float lo, hi;
            unpackf2(va, lo, hi);
            gp[(size_t)k0 * NPIX] = lo;
            gp[(size_t)(k0 + 1) * NPIX] = hi;
        }
    }
}

// ---------------- shuffle-based rolling 3x3 conv (float4 per lane) ------------
struct F4 { float x, y, z, w; };

__device__ __forceinline__ void conv_rows(float4 v, int lane, const float* w,
                                          float4& h0, float4& h1, float4& h2) {
    float l = __shfl_up_sync(0xffffffffu, v.w, 1);
    float rr = __shfl_down_sync(0xffffffffu, v.x, 1);
    if (lane == 0) l = 0.f;
    if (lane == 31) rr = 0.f;
    float lx = l, ly = v.x, lz = v.y, lw = v.z;
    float rx = v.y, ry = v.z, rz = v.w, rw = rr;
#define HROW(H, W0, W1, W2)                                   \
    H.x = W0 * lx + W1 * v.x + W2 * rx;                       \
    H.y = W0 * ly + W1 * v.y + W2 * ry;                       \
    H.z = W0 * lz + W1 * v.z + W2 * rz;                       \
    H.w = W0 * lw + W1 * v.w + W2 * rw;
    HROW(h0, w[0], w[1], w[2])
    HROW(h1, w[3], w[4], w[5])
    HROW(h2, w[6], w[7], w[8])
#undef HROW
}

__device__ __forceinline__ float4 ld_row(const float* __restrict__ base, int r, int lane) {
    if ((unsigned)r < 128u) return ((const float4*)(base + r * 128))[lane];
    return make_float4(0.f, 0.f, 0.f, 0.f);
}

// ---------------- K4: conv + partial stats ----------------
__global__ void __launch_bounds__(128) k_stats(const float* __restrict__ cw,
                                               const float* __restrict__ cb) {
    int blk = blockIdx.x;          // bd*2 + half
    int bd = blk >> 1;
    int d = bd & 15;
    int half = blk & 1;
    int tid = threadIdx.x;
    int lane = tid & 31, wp = tid >> 5;
    int R0 = half * 64 + wp * 16;
    float w[9];
#pragma unroll
    for (int t = 0; t < 9; ++t) w[t] = cw[d * 9 + t];
    float bias = cb[d];
    const float* base = g_img + (size_t)bd * NPIX;

    float4 A = make_float4(0, 0, 0, 0), B = make_float4(0, 0, 0, 0);
    float s = 0.f, sq = 0.f;
#pragma unroll 2
    for (int r = R0 - 1; r <= R0 + 16; ++r) {
        float4 v = ld_row(base, r, lane);
        float4 h0, h1, h2;
        conv_rows(v, lane, w, h0, h1, h2);
        if (r >= R0 + 1) {
            float vx = A.x + h2.x + bias, vy = A.y + h2.y + bias;
            float vz = A.z + h2.z + bias, vw = A.w + h2.w + bias;
            s += vx + vy + vz + vw;
            sq += vx * vx + vy * vy + vz * vz + vw * vw;
        }
        A.x = B.x + h1.x; A.y = B.y + h1.y; A.z = B.z + h1.z; A.w = B.w + h1.w;
        B = h0;
    }
#pragma unroll
    for (int off = 16; off; off >>= 1) {
        s += __shfl_down_sync(0xffffffffu, s, off);
        sq += __shfl_down_sync(0xffffffffu, sq, off);
    }
    __shared__ float rs[4], rq[4];
    if (lane == 0) { rs[wp] = s; rq[wp] = sq; }
    __syncthreads();
    if (tid == 0) {
        g_ps[blk] = rs[0] + rs[1] + rs[2] + rs[3];
        g_pq[blk] = rq[0] + rq[1] + rq[2] + rq[3];
    }
}

// ---------------- K5: conv (recompute) + BN + write out ----------------
__global__ void __launch_bounds__(128) k_out(const float* __restrict__ cw,
                                             const float* __restrict__ cb,
                                             const float* __restrict__ gamma,
                                             const float* __restrict__ beta,
                                             float* __restrict__ out) {
    int blk = blockIdx.x;
    int bd = blk >> 1;
    int d = bd & 15;
    int half = blk & 1;
    int tid = threadIdx.x;
    int lane = tid & 31, wp = tid >> 5;
    int R0 = half * 64 + wp * 16;

    __shared__ float smu, ssc;
    if (tid == 0) {
        double S = 0.0, Q = 0.0;
#pragma unroll
        for (int b = 0; b < 8; ++b)
#pragma unroll
            for (int h = 0; h < 2; ++h) {
                int idx = (b * DD + d) * 2 + h;
                S += (double)g_ps[idx];
                Q += (double)g_pq[idx];
            }
        double n = 131072.0;
        double mu = S / n;
        double var = Q / n - mu * mu;
        smu = (float)mu;
        ssc = rsqrtf((float)var + 1e-5f) * gamma[d];
    }
    float w[9];
#pragma unroll
    for (int t = 0; t < 9; ++t) w[t] = cw[d * 9 + t];
    float bias = cb[d];
    const float* base = g_img + (size_t)bd * NPIX;
    __syncthreads();
    float mu = smu, sc = ssc, bt = beta[d];

    float4 A = make_float4(0, 0, 0, 0), B = make_float4(0, 0, 0, 0);
    float4* op = (float4*)(out + (size_t)bd * NPIX) + lane;
#pragma unroll 2
    for (int r = R0 - 1; r <= R0 + 16; ++r) {
        float4 v = ld_row(base, r, lane);
        float4 h0, h1, h2;
        conv_rows(v, lane, w, h0, h1, h2);
        if (r >= R0 + 1) {
            float4 o;
            o.x = (A.x + h2.x + bias - mu) * sc + bt;
            o.y = (A.y + h2.y + bias - mu) * sc + bt;
            o.z = (A.z + h2.z + bias - mu) * sc + bt;
            o.w = (A.w + h2.w + bias - mu) * sc + bt;
            op[(r - 1) * 32] = o;
        }
        A.x = B.x + h1.x; A.y = B.y + h1.y; A.z = B.z + h1.z; A.w = B.w + h1.w;
        B = h0;
    }
}

extern "C" void kernel_launch(void* const* d_in, const int* in_sizes, int n_in,
                              void* d_out, int out_size) {
    const float* x = (const float*)d_in[0];
    const float* Wr = (const float*)d_in[1];
    const float* br = (const float*)d_in[2];
    const float* Wi = (const float*)d_in[3];
    const float* bi = (const float*)d_in[4];
    const float* cw = (const float*)d_in[5];
    const float* cb = (const float*)d_in[6];
    const float* gamma = (const float*)d_in[7];
    const float* beta = (const float*)d_in[8];
    float* out = (float*)d_out;

    k_prep1<<<16, 256>>>(Wr, Wi);
    k_prep2<<<16, 256>>>(br, bi);
    k_main<<<1024, 128>>>(x);
    k_stats<<<256, 128>>>(cw, cb);
    k_out<<<256, 128>>>(cw, cb, gamma, beta, out);
}

// round 4
// speedup vs baseline: 1.4527x; 1.0760x over previous
#include <cuda_runtime.h>

#define BATCH 8
#define HH 2048
#define WW 2048
#define PATCH 16
#define DD 16
#define FEAT 256
#define NPIX (128 * 128)

typedef unsigned long long ull;
typedef unsigned int uint;

// ---------------- device scratch ----------------
__device__ float g_tc[256];
__device__ float g_ts[256];
__device__ float g_R[DD][FEAT];
__device__ float g_I[DD][FEAT];
__device__ __align__(16) float2 g_M[FEAT][DD / 2];   // M[f][k] pairs along k
__device__ float g_c[DD];
__device__ float g_img[BATCH * DD * NPIX];           // 8 MB [b][d][i][j]
__device__ float g_ps[2048];                         // partial sums [bd*16+slice]
__device__ float g_pq[2048];

// ---------------- packed f32x2 helpers ----------------
__device__ __forceinline__ ull packf2(float lo, float hi) {
    ull r; asm("mov.b64 %0, {%1, %2};" : "=l"(r) : "f"(lo), "f"(hi)); return r;
}
__device__ __forceinline__ void fmaf2(ull& d, ull a, ull b) {
    asm("fma.rn.f32x2 %0, %1, %2, %0;" : "+l"(d) : "l"(a), "l"(b));
}
__device__ __forceinline__ ull addf2(ull a, ull b) {
    ull r; asm("add.rn.f32x2 %0, %1, %2;" : "=l"(r) : "l"(a), "l"(b)); return r;
}
__device__ __forceinline__ void unpackf2(ull v, float& lo, float& hi) {
    asm("mov.b64 {%0, %1}, %2;" : "=f"(lo), "=f"(hi) : "l"(v));
}
__device__ __forceinline__ void lds_v2u64(ull& a, ull& b, uint addr) {
    asm volatile("ld.shared.v2.u64 {%0, %1}, [%2];" : "=l"(a), "=l"(b) : "r"(addr));
}
__device__ __forceinline__ void pref_l2(const void* p) {
    asm volatile("prefetch.global.L2 [%0];" :: "l"(p));
}

// ---------------- K1: table + R[j,f], I[j,f] ----------------
__global__ void k_prep1(const float* __restrict__ Wr, const float* __restrict__ Wi) {
    __shared__ float sc[256], ss[256], wr[256], wi[256];
    int f = threadIdx.x, j = blockIdx.x;
    float s, c;
    sincospif((float)f * (1.0f / 128.0f), &s, &c);
    sc[f] = c; ss[f] = s;
    if (j == 0) { g_tc[f] = c; g_ts[f] = s; }
    wr[f] = Wr[j * FEAT + f]; wi[f] = Wi[j * FEAT + f];
    __syncthreads();
    float R = 0.f, I = 0.f;
    for (int d = 0; d < 256; ++d) {
        int t = (d * f) & 255;
        float cc = sc[t], s2 = ss[t];
        R += wr[d] * cc + wi[d] * s2;
        I += wi[d] * cc - wr[d] * s2;
    }
    g_R[j][f] = R; g_I[j][f] = I;
}

// ---------------- K2: M[f,k], c[k] ----------------
__global__ void k_prep2(const float* __restrict__ br, const float* __restrict__ bi) {
    int e = blockIdx.x * 256 + threadIdx.x;
    int f = e >> 4, k = e & 15;
    float m = 0.f;
    for (int j = 0; j < DD; ++j) {
        int t = (16 * j * k) & 255;
        m += g_R[j][f] * g_tc[t] - g_I[j][f] * g_ts[t];
    }
    ((float*)g_M)[f * DD + k] = m * (1.0f / 16.0f);
    if (e < DD) {
        float cc = 0.f;
        for (int j = 0; j < DD; ++j) {
            int t = (16 * j * e) & 255;
            cc += (br[j] - bi[j]) * g_tc[t] - (br[j] + bi[j]) * g_ts[t];
        }
        g_c[e] = cc * (1.0f / 16.0f);
    }
}

// ---------------- K3: main patch GEMM ----------------
// Warp = 64 adjacent patches (8 streams), k split across warp pairs (kh).
// lane l: a = l>>2 (patch sub-index), q = l&3 (s2 quad).
// Per s1: 8 coalesced LDG.128 (4KB/warp, L2-prefetched 2 rows ahead),
// 8 LDS.128 of M (swizzled, conflict-free, 8-lane broadcast) feed 256 FMA2.
__global__ void __launch_bounds__(128, 4) k_main(const float* __restrict__ x) {
    __shared__ uint4 sM[FEAT * 4];   // row f: unit m stored at col (m+(f>>2))&3
    __shared__ float scc[DD];
    int tid = threadIdx.x;
    {
        const uint4* gm = (const uint4*)g_M;
        for (int f = tid; f < 256; f += 128)
#pragma unroll
            for (int m = 0; m < 4; ++m)
                sM[f * 4 + ((m + (f >> 2)) & 3)] = gm[f * 4 + m];
        if (tid < DD) scc[tid] = g_c[tid];
    }
    __syncthreads();

    uint sMaddr = (uint)__cvta_generic_to_shared(sM);
    int lane = tid & 31;
    int warp = tid >> 5;
    int unit = blockIdx.x * 2 + (warp & 1);   // 2048 units (b, ph, seg)
    int kh = warp >> 1;                       // k half: pairs kh*4 .. kh*4+3
    int b = unit >> 8;
    int r = unit & 255;
    int ph = r >> 1;
    int seg = r & 1;                          // 64-patch column segment
    int a = lane >> 2;
    int q = lane & 3;

    const float* base = x + (size_t)b * HH * WW + (size_t)(ph * PATCH) * WW + seg * 1024;

    ull acc[8][4];
    ull z = packf2(0.f, 0.f);
#pragma unroll
    for (int t = 0; t < 8; ++t)
#pragma unroll
        for (int p = 0; p < 4; ++p) acc[t][p] = z;

    const float4* rp = (const float4*)base;
    float4 cur[8];
#pragma unroll
    for (int t = 0; t < 8; ++t) cur[t] = rp[t * 32 + lane];
    pref_l2(base + (size_t)1 * WW + lane * 32);
    pref_l2(base + (size_t)2 * WW + lane * 32);

    uint c0 = (uint)(((2 * kh + q) & 3) << 4);
    uint c1 = (uint)(((2 * kh + 1 + q) & 3) << 4);

#pragma unroll 1
    for (int s1 = 0; s1 < PATCH; ++s1) {
        if (s1 < 13) pref_l2(base + (size_t)(s1 + 3) * WW + lane * 32);
        uint rowbase = sMaddr + (uint)(s1 * 16 + q * 4) * 64;
#pragma unroll
        for (int e = 0; e < 4; ++e) {
            uint ra = rowbase + (uint)e * 64;
            ull mk0, mk1, mk2, mk3;
            lds_v2u64(mk0, mk1, ra + c0);
            lds_v2u64(mk2, mk3, ra + c1);
#pragma unroll
            for (int t = 0; t < 8; ++t) {
                float xv = (e == 0) ? cur[t].x : (e == 1) ? cur[t].y
                         : (e == 2) ? cur[t].z : cur[t].w;
                ull vp = packf2(xv, xv);
                fmaf2(acc[t][0], vp, mk0);
                fmaf2(acc[t][1], vp, mk1);
                fmaf2(acc[t][2], vp, mk2);
                fmaf2(acc[t][3], vp, mk3);
            }
        }
        if (s1 < 15) {
            const float4* rn = (const float4*)(base + (size_t)(s1 + 1) * WW);
#pragma unroll
            for (int t = 0; t < 8; ++t) cur[t] = rn[t * 32 + lane];
        }
    }

    // reduce-scatter acc[t][0..3] over the 4 quad lanes -> 1 k-pair per lane
    int lp = ((q & 1) << 1) | ((q & 2) >> 1);   // local pair owned after 2 rounds
    int k0 = (4 * kh + lp) * 2;
    ull cbias = packf2(scc[k0], scc[k0 + 1]);
    float* gp = g_img + (size_t)b * DD * NPIX + ph * 128 + seg * 64;
#pragma unroll
    for (int t = 0; t < 8; ++t) {
        ull tmp0, tmp1, fin;
        {
            ull send = (q & 1) ? acc[t][0] : acc[t][2];
            ull keep = (q & 1) ? acc[t][2] : acc[t][0];
            tmp0 = addf2(keep, __shfl_xor_sync(0xffffffffu, send, 1));
            send = (q & 1) ? acc[t][1] : acc[t][3];
            keep = (q & 1) ? acc[t][3] : acc[t][1];
            tmp1 = addf2(keep, __shfl_xor_sync(0xffffffffu, send, 1));
        }
        {
            ull send = (q & 2) ? tmp0 : tmp1;
            ull keep = (q & 2) ? tmp1 : tmp0;
            fin = addf2(keep, __shfl_xor_sync(0xffffffffu, send, 2));
        }
        ull v = addf2(fin, cbias);
        float lo, hi;
        unpackf2(v, lo, hi);
        int col = t * 8 + a;
        gp[(size_t)k0 * NPIX + col] = lo;
        gp[(size_t)(k0 + 1) * NPIX + col] = hi;
    }
}

// ---------------- rolling scalar 3x3 conv: one column per thread --------------
__device__ __forceinline__ void conv_h(const float* __restrict__ base, int r, int j,
                                       const float* w, float& h0, float& h1, float& h2) {
    float l = 0.f, m = 0.f, rr = 0.f;
    if ((unsigned)r < 128u) {
        const float* rowp = base + r * 128;
        m = rowp[j];
        if (j > 0) l = rowp[j - 1];
        if (j < 127) rr = rowp[j + 1];
    }
    h0 = w[0] * l + w[1] * m + w[2] * rr;
    h1 = w[3] * l + w[4] * m + w[5] * rr;
    h2 = w[6] * l + w[7] * m + w[8] * rr;
}

// ---------------- K4: conv + per-slice partial stats ----------------
__global__ void __launch_bounds__(128) k_stats(const float* __restrict__ cw,
                                               const float* __restrict__ cb) {
    int blk = blockIdx.x;            // bd*16 + slice
    int bd = blk >> 4;
    int d = bd & 15;
    int r0 = (blk & 15) * 8;
    int j = threadIdx.x;
    float w[9];
#pragma unroll
    for (int t = 0; t < 9; ++t) w[t] = cw[d * 9 + t];
    float bias = cb[d];
    const float* base = g_img + (size_t)bd * NPIX;

    float A = 0.f, B = 0.f, s = 0.f, sq = 0.f;
#pragma unroll
    for (int r = r0 - 1; r <= r0 + 8; ++r) {
        float h0, h1, h2;
        conv_h(base, r, j, w, h0, h1, h2);
        if (r >= r0 + 1) {
            float v = A + h2 + bias;
            s += v; sq += v * v;
        }
        A = B + h1;
        B = h0;
    }
#pragma unroll
    for (int off = 16; off; off >>= 1) {
        s += __shfl_down_sync(0xffffffffu, s, off);
        sq += __shfl_down_sync(0xffffffffu, sq, off);
    }
    __shared__ float rs[4], rq[4];
    if ((j & 31) == 0) { rs[j >> 5] = s; rq[j >> 5] = sq; }
    __syncthreads();
    if (j == 0) {
        g_ps[blk] = rs[0] + rs[1] + rs[2] + rs[3];
        g_pq[blk] = rq[0] + rq[1] + rq[2] + rq[3];
    }
}

// ---------------- K5: BN finalize (in-block) + conv + BN apply + write --------
__global__ void __launch_bounds__(128) k_out(const float* __restrict__ cw,
                                             const float* __restrict__ cb,
                                             const float* __restrict__ gamma,
                                             const float* __restrict__ beta,
                                             float* __restrict__ out) {
    int blk = blockIdx.x;
    int bd = blk >> 4;
    int d = bd & 15;
    int r0 = (blk & 15) * 8;
    int j = threadIdx.x;

    // parallel reduce the 128 partials (b x 16 slices) for this d
    __shared__ float sp[128], sq2[128];
    __shared__ float smu, ssc;
    {
        int bb = j >> 4, sl = j & 15;
        int idx = ((bb * DD + d) << 4) + sl;
        sp[j] = g_ps[idx];
        sq2[j] = g_pq[idx];
    }
    __syncthreads();
    for (int off = 64; off; off >>= 1) {
        if (j < off) { sp[j] += sp[j + off]; sq2[j] += sq2[j + off]; }
        __syncthreads();
    }
    if (j == 0) {
        float n = 131072.0f;
        float mu = sp[0] / n;
        float var = sq2[0] / n - mu * mu;
        smu = mu;
        ssc = rsqrtf(var + 1e-5f) * gamma[d];
    }
    float w[9];
#pragma unroll
    for (int t = 0; t < 9; ++t) w[t] = cw[d * 9 + t];
    float bias = cb[d];
    const float* base = g_img + (size_t)bd * NPIX;
    __syncthreads();
    float mu = smu, sc = ssc, bt = beta[d];

    float A = 0.f, B = 0.f;
    float* op = out + (size_t)bd * NPIX + j;
#pragma unroll
    for (int r = r0 - 1; r <= r0 + 8; ++r) {
        float h0, h1, h2;
        conv_h(base, r, j, w, h0, h1, h2);
        if (r >= r0 + 1) {
            float v = A + h2 + bias;
            op[(r - 1) * 128] = (v - mu) * sc + bt;
        }
        A = B + h1;
        B = h0;
    }
}

extern "C" void kernel_launch(void* const* d_in, const int* in_sizes, int n_in,
                              void* d_out, int out_size) {
    const float* x = (const float*)d_in[0];
    const float* Wr = (const float*)d_in[1];
    const float* br = (const float*)d_in[2];
    const float* Wi = (const float*)d_in[3];
    const float* bi = (const float*)d_in[4];
    const float* cw = (const float*)d_in[5];
    const float* cb = (const float*)d_in[6];
    const float* gamma = (const float*)d_in[7];
    const float* beta = (const float*)d_in[8];
    float* out = (float*)d_out;

    k_prep1<<<16, 256>>>(Wr, Wi);
    k_prep2<<<16, 256>>>(br, bi);
    k_main<<<1024, 128>>>(x);
    k_stats<<<2048, 128>>>(cw, cb);
    k_out<<<2048, 128>>>(cw, cb, gamma, beta, out);
}